// round 10
// baseline (speedup 1.0000x reference)
#include <cuda_runtime.h>
#include <cstdint>

// Model_25855703122577: inputs [8192,784,1] f32, W_ih[30,1], W_hh[30,30],
// b_mod[30], W_lin[10,30], b_lin[10] -> out [8192,10] f32
#define RB    8192
#define RT    784
#define RH    30
#define RC    10
#define KP    15       // k-pairs (exact)
#define TPB   32       // one warp per block
#define SLOTS 2        // batches per warp, processed serially per step
#define HSTR  36       // floats per slot (144B, 16B-aligned)

typedef unsigned long long u64;

__device__ __forceinline__ u64 fmul2(u64 a, u64 b) {
    u64 d; asm("mul.rn.f32x2 %0, %1, %2;" : "=l"(d) : "l"(a), "l"(b)); return d;
}
__device__ __forceinline__ u64 ffma2(u64 a, u64 b, u64 c) {
    u64 d; asm("fma.rn.f32x2 %0, %1, %2, %3;" : "=l"(d) : "l"(a), "l"(b), "l"(c)); return d;
}
__device__ __forceinline__ u64 pack2(float lo, float hi) {
    u64 d; asm("mov.b64 %0, {%1, %2};" : "=l"(d) : "f"(lo), "f"(hi)); return d;
}
__device__ __forceinline__ void unpack2(u64 v, float& lo, float& hi) {
    asm("mov.b64 {%0, %1}, %2;" : "=f"(lo), "=f"(hi) : "l"(v));
}

// One batch sub-step for this lane's single row. h read as 8 LDS.128 chunks
// through a 2-deep ring interleaved with the chain. x*W_ih is folded into the
// accumulator init: acc = {x*wih, 0}, so z = lo+hi includes it.
__device__ __forceinline__ float row_step(
    float x, const u64 (&w)[KP], u64 wihx, float bm,
    const float* __restrict__ hsrc)   // slot base (32 floats, pads zero)
{
    const ulonglong2* hp = reinterpret_cast<const ulonglong2*>(hsrc);
    ulonglong2 rb0 = hp[0];
    ulonglong2 rb1 = hp[1];

    u64 acc = fmul2(wihx, pack2(x, x));        // {x*wih, 0}
    acc = ffma2(w[0],  rb0.x, acc);
    acc = ffma2(w[1],  rb0.y, acc);  rb0 = hp[2];
    acc = ffma2(w[2],  rb1.x, acc);
    acc = ffma2(w[3],  rb1.y, acc);  rb1 = hp[3];
    acc = ffma2(w[4],  rb0.x, acc);
    acc = ffma2(w[5],  rb0.y, acc);  rb0 = hp[4];
    acc = ffma2(w[6],  rb1.x, acc);
    acc = ffma2(w[7],  rb1.y, acc);  rb1 = hp[5];
    acc = ffma2(w[8],  rb0.x, acc);
    acc = ffma2(w[9],  rb0.y, acc);  rb0 = hp[6];
    acc = ffma2(w[10], rb1.x, acc);
    acc = ffma2(w[11], rb1.y, acc);  rb1 = hp[7];
    acc = ffma2(w[12], rb0.x, acc);
    acc = ffma2(w[13], rb0.y, acc);
    acc = ffma2(w[14], rb1.x, acc);            // pair 15 = zero pad: skipped

    float lo, hi;
    unpack2(acc, lo, hi);
    float z = lo + hi;
    // modReLU: copysign(relu(|z|+b), z); z==0 -> +0 (pad rows stay 0 forever)
    float m = fmaxf(fabsf(z) + bm, 0.0f);
    return copysignf(m, z);
}

extern "C" __global__ void __launch_bounds__(TPB, 28)
rnn_modrelu_kernel(const float* __restrict__ inputs,  // [B, T]
                   const float* __restrict__ W_ih,    // [H]
                   const float* __restrict__ W_hh,    // [H, H]
                   const float* __restrict__ b_mod,   // [H]
                   const float* __restrict__ W_lin,   // [C, H]
                   const float* __restrict__ b_lin,   // [C]
                   float* __restrict__ out)           // [B, C]
{
    __shared__ __align__(16) float hbuf[2][SLOTS][HSTR];

    const int lane = threadIdx.x;        // 0..31 == this lane's hidden row
    const int b0   = blockIdx.x * SLOTS;
    const int b1   = b0 + 1;

    // ---- register weight slice: 1 row x 15 pairs = 30 regs ----
    u64 w[KP];
    u64 wihx;
    float bm;
    if (lane < RH) {
        const u64* wr = reinterpret_cast<const u64*>(W_hh + lane * RH);
#pragma unroll
        for (int p = 0; p < KP; p++) w[p] = wr[p];
        wihx = pack2(W_ih[lane], 0.0f);
        bm   = b_mod[lane];
    } else {                 // rows 30,31: all-zero -> h pads stay exactly 0
#pragma unroll
        for (int p = 0; p < KP; p++) w[p] = 0ULL;
        wihx = 0ULL;
        bm   = 0.0f;
    }

    // h0 = 0 (32 floats per slot; floats 32..35 never read)
    hbuf[0][0][lane] = 0.0f;
    hbuf[0][1][lane] = 0.0f;
    __syncwarp();

    const float* xrA = inputs + (size_t)b0 * RT;
    const float* xrB = inputs + (size_t)b1 * RT;

#pragma unroll 1
    for (int t0 = 0; t0 < RT; t0 += 2) {
        const float2 xa = *reinterpret_cast<const float2*>(xrA + t0);
        const float2 xb = *reinterpret_cast<const float2*>(xrB + t0);

        // step t0: buf0 -> buf1
        float hA = row_step(xa.x, w, wihx, bm, &hbuf[0][0][0]);
        float hB = row_step(xb.x, w, wihx, bm, &hbuf[0][1][0]);
        hbuf[1][0][lane] = hA;
        hbuf[1][1][lane] = hB;
        __syncwarp();

        // step t0+1: buf1 -> buf0
        hA = row_step(xa.y, w, wihx, bm, &hbuf[1][0][0]);
        hB = row_step(xb.y, w, wihx, bm, &hbuf[1][1][0]);
        hbuf[0][0][lane] = hA;
        hbuf[0][1][lane] = hB;
        __syncwarp();
    }
    // T=784 even -> final h in buffer 0

    // ---- fused classifier: out[b][c] = h . W_lin[c] + b_lin[c] ----
    if (lane < RC) {
        const float* wl = W_lin + lane * RH;
        float acc0 = b_lin[lane];
        float acc1 = acc0;
        const float* h0 = &hbuf[0][0][0];
        const float* h1 = &hbuf[0][1][0];
#pragma unroll
        for (int k = 0; k < RH; k++) {
            acc0 = fmaf(h0[k], wl[k], acc0);
            acc1 = fmaf(h1[k], wl[k], acc1);
        }
        out[(size_t)b0 * RC + lane] = acc0;
        out[(size_t)b1 * RC + lane] = acc1;
    }
}

extern "C" void kernel_launch(void* const* d_in, const int* in_sizes, int n_in,
                              void* d_out, int out_size) {
    const float* inputs = (const float*)d_in[0];
    const float* W_ih   = (const float*)d_in[1];
    const float* W_hh   = (const float*)d_in[2];
    const float* b_mod  = (const float*)d_in[3];
    const float* W_lin  = (const float*)d_in[4];
    const float* b_lin  = (const float*)d_in[5];
    float* out = (float*)d_out;

    dim3 grid(RB / SLOTS);   // 4096 one-warp blocks; 28/SM -> ALL resident
    dim3 block(TPB);
    rnn_modrelu_kernel<<<grid, block>>>(inputs, W_ih, W_hh, b_mod,
                                        W_lin, b_lin, out);
}

// round 11
// speedup vs baseline: 1.1093x; 1.1093x over previous
#include <cuda_runtime.h>
#include <cstdint>

// Model_25855703122577: inputs [8192,784,1] f32, W_ih[30,1], W_hh[30,30],
// b_mod[30], W_lin[10,30], b_lin[10] -> out [8192,10] f32
#define RB    8192
#define RT    784
#define RH    30
#define RC    10
#define GRP   16       // lanes per batch element (2 parallel groups per warp)
#define RPT   2        // rows per lane (16*2 = 32; rows 30,31 zero pads)
#define KP    15       // k-pairs (exact)
#define TPB   32       // one warp per block
#define SLOTS 4        // batches per warp: 2 parallel groups x 2 serial
#define HSTR  36       // floats per slot (144B, 16B-aligned)

typedef unsigned long long u64;

__device__ __forceinline__ u64 fmul2(u64 a, u64 b) {
    u64 d; asm("mul.rn.f32x2 %0, %1, %2;" : "=l"(d) : "l"(a), "l"(b)); return d;
}
__device__ __forceinline__ u64 ffma2(u64 a, u64 b, u64 c) {
    u64 d; asm("fma.rn.f32x2 %0, %1, %2, %3;" : "=l"(d) : "l"(a), "l"(b), "l"(c)); return d;
}
__device__ __forceinline__ u64 pack2(float lo, float hi) {
    u64 d; asm("mov.b64 %0, {%1, %2};" : "=l"(d) : "f"(lo), "f"(hi)); return d;
}
__device__ __forceinline__ void unpack2(u64 v, float& lo, float& hi) {
    asm("mov.b64 {%0, %1}, %2;" : "=f"(lo), "=f"(hi) : "l"(v));
}

// One t-step for this lane's 2 rows across 2 batches (A,B): 4 interleaved
// FFMA2 chains, h streamed as 2x8 LDS.128 through 2-deep rings.
// x*W_ih is folded into the accumulator init: acc = wihx * {x,x} = {x*wih, 0}.
__device__ __forceinline__ void rnn_step(
    float xa, float xb,
    const u64 (&w)[RPT][KP],
    const u64 (&wihx)[RPT],
    const float (&bm)[RPT],
    const float* __restrict__ hsrcA, const float* __restrict__ hsrcB,
    float* __restrict__ hdstA, float* __restrict__ hdstB)
{
    const ulonglong2* hpA = reinterpret_cast<const ulonglong2*>(hsrcA);
    const ulonglong2* hpB = reinterpret_cast<const ulonglong2*>(hsrcB);

    ulonglong2 ringA[2], ringB[2];
    ringA[0] = hpA[0]; ringB[0] = hpB[0];
    ringA[1] = hpA[1]; ringB[1] = hpB[1];

    const u64 xxA = pack2(xa, xa);
    const u64 xxB = pack2(xb, xb);
    u64 aA[RPT], aB[RPT];
#pragma unroll
    for (int r = 0; r < RPT; r++) {
        aA[r] = fmul2(wihx[r], xxA);   // {x*wih, 0}
        aB[r] = fmul2(wihx[r], xxB);
    }

#pragma unroll
    for (int c = 0; c < 8; c++) {
        const ulonglong2 vA = ringA[c & 1];
        const ulonglong2 vB = ringB[c & 1];
        if (c < 6) {                   // prefetch chunk c+2 into freed slot
            ringA[c & 1] = hpA[c + 2];
            ringB[c & 1] = hpB[c + 2];
        }
#pragma unroll
        for (int r = 0; r < RPT; r++) {
            aA[r] = ffma2(w[r][2 * c], vA.x, aA[r]);
            aB[r] = ffma2(w[r][2 * c], vB.x, aB[r]);
        }
        if (2 * c + 1 < KP) {          // pair 15 is the zero pad: skip
#pragma unroll
            for (int r = 0; r < RPT; r++) {
                aA[r] = ffma2(w[r][2 * c + 1], vA.y, aA[r]);
                aB[r] = ffma2(w[r][2 * c + 1], vB.y, aB[r]);
            }
        }
    }

    float hvA[RPT], hvB[RPT];
#pragma unroll
    for (int r = 0; r < RPT; r++) {
        float lo, hi;
        unpack2(aA[r], lo, hi);
        float zA = lo + hi;
        unpack2(aB[r], lo, hi);
        float zB = lo + hi;
        // modReLU: copysign(relu(|z|+b), z); z==0 -> +0 (pad rows stay 0)
        float mA = fmaxf(fabsf(zA) + bm[r], 0.0f);
        float mB = fmaxf(fabsf(zB) + bm[r], 0.0f);
        hvA[r] = copysignf(mA, zA);
        hvB[r] = copysignf(mB, zB);
    }
    *reinterpret_cast<float2*>(hdstA) = make_float2(hvA[0], hvA[1]);
    *reinterpret_cast<float2*>(hdstB) = make_float2(hvB[0], hvB[1]);
    __syncwarp();
}

extern "C" __global__ void __launch_bounds__(TPB)
rnn_modrelu_kernel(const float* __restrict__ inputs,  // [B, T]
                   const float* __restrict__ W_ih,    // [H]
                   const float* __restrict__ W_hh,    // [H, H]
                   const float* __restrict__ b_mod,   // [H]
                   const float* __restrict__ W_lin,   // [C, H]
                   const float* __restrict__ b_lin,   // [C]
                   float* __restrict__ out)           // [B, C]
{
    __shared__ __align__(16) float hbuf[2][SLOTS][HSTR];

    const int lane = threadIdx.x;       // 0..31
    const int sub  = lane & (GRP - 1);  // 0..15 row-slice
    const int g    = lane >> 4;         // 0..1 parallel group
    const int sA   = g;                 // serial batch A slot
    const int sB   = g + 2;             // serial batch B slot
    const int bA   = blockIdx.x * SLOTS + sA;
    const int bB   = blockIdx.x * SLOTS + sB;

    // ---- register weight slice: 2 rows x 15 pairs = 60 regs ----
    u64 w[RPT][KP];
    u64 wihx[RPT];
    float bm[RPT];
#pragma unroll
    for (int r = 0; r < RPT; r++) {
        const int row = sub * RPT + r;
        if (row < RH) {
            const u64* wr = reinterpret_cast<const u64*>(W_hh + row * RH);
#pragma unroll
            for (int p = 0; p < KP; p++) w[r][p] = wr[p];
            wihx[r] = pack2(W_ih[row], 0.0f);
            bm[r]   = b_mod[row];
        } else {            // rows 30,31: all-zero -> stay exactly 0 forever
#pragma unroll
            for (int p = 0; p < KP; p++) w[r][p] = 0ULL;
            wihx[r] = 0ULL;
            bm[r]   = 0.0f;
        }
    }

    // h0 = 0 (each lane zeroes its float2 in both its slots)
    *reinterpret_cast<float2*>(&hbuf[0][sA][sub * 2]) = make_float2(0, 0);
    *reinterpret_cast<float2*>(&hbuf[0][sB][sub * 2]) = make_float2(0, 0);
    __syncwarp();

    const float* xrA = inputs + (size_t)bA * RT;
    const float* xrB = inputs + (size_t)bB * RT;

#pragma unroll 1
    for (int t0 = 0; t0 < RT; t0 += 4) {
        const float4 x4a = *reinterpret_cast<const float4*>(xrA + t0);
        const float4 x4b = *reinterpret_cast<const float4*>(xrB + t0);
        rnn_step(x4a.x, x4b.x, w, wihx, bm,
                 &hbuf[0][sA][0], &hbuf[0][sB][0],
                 &hbuf[1][sA][sub * 2], &hbuf[1][sB][sub * 2]);
        rnn_step(x4a.y, x4b.y, w, wihx, bm,
                 &hbuf[1][sA][0], &hbuf[1][sB][0],
                 &hbuf[0][sA][sub * 2], &hbuf[0][sB][sub * 2]);
        rnn_step(x4a.z, x4b.z, w, wihx, bm,
                 &hbuf[0][sA][0], &hbuf[0][sB][0],
                 &hbuf[1][sA][sub * 2], &hbuf[1][sB][sub * 2]);
        rnn_step(x4a.w, x4b.w, w, wihx, bm,
                 &hbuf[1][sA][0], &hbuf[1][sB][0],
                 &hbuf[0][sA][sub * 2], &hbuf[0][sB][sub * 2]);
    }
    // T=784 even -> final h in buffer 0

    // ---- fused classifier: out[b][c] = h . W_lin[c] + b_lin[c] ----
    if (sub < RC) {
        const float* wl = W_lin + sub * RH;
        float accA = b_lin[sub];
        float accB = accA;
        const float* hA = &hbuf[0][sA][0];
        const float* hB = &hbuf[0][sB][0];
#pragma unroll
        for (int k = 0; k < RH; k++) {
            accA = fmaf(hA[k], wl[k], accA);
            accB = fmaf(hB[k], wl[k], accB);
        }
        out[(size_t)bA * RC + sub] = accA;
        out[(size_t)bB * RC + sub] = accB;
    }
}

extern "C" void kernel_launch(void* const* d_in, const int* in_sizes, int n_in,
                              void* d_out, int out_size) {
    const float* inputs = (const float*)d_in[0];
    const float* W_ih   = (const float*)d_in[1];
    const float* W_hh   = (const float*)d_in[2];
    const float* b_mod  = (const float*)d_in[3];
    const float* W_lin  = (const float*)d_in[4];
    const float* b_lin  = (const float*)d_in[5];
    float* out = (float*)d_out;

    dim3 grid(RB / SLOTS);   // 2048 one-warp blocks: 13.8/SM, all resident
    dim3 block(TPB);
    rnn_modrelu_kernel<<<grid, block>>>(inputs, W_ih, W_hh, b_mod,
                                        W_lin, b_lin, out);
}

// round 12
// speedup vs baseline: 1.1962x; 1.0784x over previous
#include <cuda_runtime.h>
#include <cstdint>

// Model_25855703122577: inputs [8192,784,1] f32, W_ih[30,1], W_hh[30,30],
// b_mod[30], W_lin[10,30], b_lin[10] -> out [8192,10] f32
#define RB    8192
#define RT    784
#define RH    30
#define RC    10
#define GRP   16       // lanes per batch element (2 parallel groups per warp)
#define RPT   2        // rows per lane (16*2 = 32; rows 30,31 zero pads)
#define KP    15       // k-pairs (exact)
#define TPB   32       // one warp per block
#define SLOTS 2        // batches per warp (one per half-warp, parallel)
#define HSTR  36       // floats per slot (144B, 16B-aligned)

typedef unsigned long long u64;

__device__ __forceinline__ u64 fmul2(u64 a, u64 b) {
    u64 d; asm("mul.rn.f32x2 %0, %1, %2;" : "=l"(d) : "l"(a), "l"(b)); return d;
}
__device__ __forceinline__ u64 ffma2(u64 a, u64 b, u64 c) {
    u64 d; asm("fma.rn.f32x2 %0, %1, %2, %3;" : "=l"(d) : "l"(a), "l"(b), "l"(c)); return d;
}
__device__ __forceinline__ u64 pack2(float lo, float hi) {
    u64 d; asm("mov.b64 %0, {%1, %2};" : "=l"(d) : "f"(lo), "f"(hi)); return d;
}
__device__ __forceinline__ void unpack2(u64 v, float& lo, float& hi) {
    asm("mov.b64 {%0, %1}, %2;" : "=f"(lo), "=f"(hi) : "l"(v));
}

// One t-step for this lane's 2 rows of its group's batch.
// h read as 8 LDS.128 through a 2-deep ring interleaved with the 2 chains.
// x*W_ih folded into accumulator init: acc = wihx*{x,x} = {x*wih, 0}.
// NOTE: no __restrict__ on h pointers — the warp-synchronous (sync-free)
// exchange relies on ptxas preserving STS->LDS program order on hbuf.
__device__ __forceinline__ void rnn_step(
    float x,
    const u64 (&w)[RPT][KP],
    const u64 (&wihx)[RPT],
    const float (&bm)[RPT],
    const float* hsrc,    // group slot base (32 floats, pads zero)
    float* hdst)          // other buffer, this lane's float2
{
    const ulonglong2* hp = reinterpret_cast<const ulonglong2*>(hsrc);
    ulonglong2 rb0 = hp[0];
    ulonglong2 rb1 = hp[1];

    const u64 xx = pack2(x, x);
    u64 a0 = fmul2(wihx[0], xx);      // {x*wih0, 0}
    u64 a1 = fmul2(wihx[1], xx);      // {x*wih1, 0}

    a0 = ffma2(w[0][0], rb0.x, a0);  a1 = ffma2(w[1][0], rb0.x, a1);
    a0 = ffma2(w[0][1], rb0.y, a0);  a1 = ffma2(w[1][1], rb0.y, a1);  rb0 = hp[2];
    a0 = ffma2(w[0][2], rb1.x, a0);  a1 = ffma2(w[1][2], rb1.x, a1);
    a0 = ffma2(w[0][3], rb1.y, a0);  a1 = ffma2(w[1][3], rb1.y, a1);  rb1 = hp[3];
    a0 = ffma2(w[0][4], rb0.x, a0);  a1 = ffma2(w[1][4], rb0.x, a1);
    a0 = ffma2(w[0][5], rb0.y, a0);  a1 = ffma2(w[1][5], rb0.y, a1);  rb0 = hp[4];
    a0 = ffma2(w[0][6], rb1.x, a0);  a1 = ffma2(w[1][6], rb1.x, a1);
    a0 = ffma2(w[0][7], rb1.y, a0);  a1 = ffma2(w[1][7], rb1.y, a1);  rb1 = hp[5];
    a0 = ffma2(w[0][8], rb0.x, a0);  a1 = ffma2(w[1][8], rb0.x, a1);
    a0 = ffma2(w[0][9], rb0.y, a0);  a1 = ffma2(w[1][9], rb0.y, a1);  rb0 = hp[6];
    a0 = ffma2(w[0][10], rb1.x, a0); a1 = ffma2(w[1][10], rb1.x, a1);
    a0 = ffma2(w[0][11], rb1.y, a0); a1 = ffma2(w[1][11], rb1.y, a1); rb1 = hp[7];
    a0 = ffma2(w[0][12], rb0.x, a0); a1 = ffma2(w[1][12], rb0.x, a1);
    a0 = ffma2(w[0][13], rb0.y, a0); a1 = ffma2(w[1][13], rb0.y, a1);
    a0 = ffma2(w[0][14], rb1.x, a0); a1 = ffma2(w[1][14], rb1.x, a1);
    // pair 15 = zero pad: skipped

    float lo0, hi0, lo1, hi1;
    unpack2(a0, lo0, hi0);
    unpack2(a1, lo1, hi1);
    float z0 = lo0 + hi0;             // includes x*wih from the init
    float z1 = lo1 + hi1;
    // modReLU: copysign(relu(|z|+b), z); z==0 -> +0 (pad rows stay 0 forever)
    float m0 = fmaxf(fabsf(z0) + bm[0], 0.0f);
    float m1 = fmaxf(fabsf(z1) + bm[1], 0.0f);
    *reinterpret_cast<float2*>(hdst) = make_float2(copysignf(m0, z0),
                                                   copysignf(m1, z1));
    // Warp-synchronous exchange: loop body has no divergent branches, so the
    // warp stays converged and STS->LDS program order suffices. Compiler-only
    // fence to forbid reordering across the step boundary:
    asm volatile("" ::: "memory");
}

extern "C" __global__ void __launch_bounds__(TPB)
rnn_modrelu_kernel(const float* __restrict__ inputs,  // [B, T]
                   const float* __restrict__ W_ih,    // [H]
                   const float* __restrict__ W_hh,    // [H, H]
                   const float* __restrict__ b_mod,   // [H]
                   const float* __restrict__ W_lin,   // [C, H]
                   const float* __restrict__ b_lin,   // [C]
                   float* __restrict__ out)           // [B, C]
{
    __shared__ __align__(16) float hbuf[2][SLOTS][HSTR];

    const int lane = threadIdx.x;       // 0..31
    const int sub  = lane & (GRP - 1);  // 0..15 row-slice
    const int grp  = lane >> 4;         // 0..1 batch group (half-warp)
    const int b    = blockIdx.x * SLOTS + grp;

    // ---- register weight slice: 2 rows x 15 pairs = 60 regs ----
    u64 w[RPT][KP];
    u64 wihx[RPT];
    float bm[RPT];
#pragma unroll
    for (int r = 0; r < RPT; r++) {
        const int row = sub * RPT + r;
        if (row < RH) {
            const u64* wr = reinterpret_cast<const u64*>(W_hh + row * RH);
#pragma unroll
            for (int p = 0; p < KP; p++) w[r][p] = wr[p];
            wihx[r] = pack2(W_ih[row], 0.0f);
            bm[r]   = b_mod[row];
        } else {            // rows 30,31: all-zero -> stay exactly 0 forever
#pragma unroll
            for (int p = 0; p < KP; p++) w[r][p] = 0ULL;
            wihx[r] = 0ULL;
            bm[r]   = 0.0f;
        }
    }

    // h0 = 0 (each lane zeroes its float2 -> all 32 floats per slot covered)
    *reinterpret_cast<float2*>(&hbuf[0][grp][sub * 2]) = make_float2(0, 0);
    __syncwarp();

    const float* xr = inputs + (size_t)b * RT;

#pragma unroll 1
    for (int t0 = 0; t0 < RT; t0 += 2) {
        const float2 x2 = *reinterpret_cast<const float2*>(xr + t0);
        rnn_step(x2.x, w, wihx, bm, &hbuf[0][grp][0], &hbuf[1][grp][sub * 2]);
        rnn_step(x2.y, w, wihx, bm, &hbuf[1][grp][0], &hbuf[0][grp][sub * 2]);
    }
    // T=784 even -> final h in buffer 0
    __syncwarp();   // one-time, before cross-lane classifier reads

    // ---- fused classifier: out[b][c] = h . W_lin[c] + b_lin[c] ----
    if (sub < RC) {
        const float* hf = &hbuf[0][grp][0];
        float acc = b_lin[sub];
        const float* wl = W_lin + sub * RH;
#pragma unroll
        for (int k = 0; k < RH; k++) acc = fmaf(hf[k], wl[k], acc);
        out[(size_t)b * RC + sub] = acc;
    }
}

extern "C" void kernel_launch(void* const* d_in, const int* in_sizes, int n_in,
                              void* d_out, int out_size) {
    const float* inputs = (const float*)d_in[0];
    const float* W_ih   = (const float*)d_in[1];
    const float* W_hh   = (const float*)d_in[2];
    const float* b_mod  = (const float*)d_in[3];
    const float* W_lin  = (const float*)d_in[4];
    const float* b_lin  = (const float*)d_in[5];
    float* out = (float*)d_out;

    dim3 grid(RB / SLOTS);   // 4096 one-warp blocks
    dim3 block(TPB);
    rnn_modrelu_kernel<<<grid, block>>>(inputs, W_ih, W_hh, b_mod,
                                        W_lin, b_lin, out);
}

// round 13
// speedup vs baseline: 1.2614x; 1.0545x over previous
#include <cuda_runtime.h>
#include <cstdint>

// Model_25855703122577: inputs [8192,784,1] f32, W_ih[30,1], W_hh[30,30],
// b_mod[30], W_lin[10,30], b_lin[10] -> out [8192,10] f32
#define RB    8192
#define RT    784
#define RH    30
#define RC    10
#define GRP   8        // lanes per batch element (4 parallel groups per warp)
#define RPT   4        // rows per lane (8*4 = 32; rows 30,31 zero pads)
#define KP    15       // k-pairs (exact)
#define TPB   32       // one warp per block
#define SLOTS 4        // batches per warp (one per 8-lane group)
#define HSTR  36       // floats per slot (144B: groups land on distinct banks)

typedef unsigned long long u64;

__device__ __forceinline__ u64 fmul2(u64 a, u64 b) {
    u64 d; asm("mul.rn.f32x2 %0, %1, %2;" : "=l"(d) : "l"(a), "l"(b)); return d;
}
__device__ __forceinline__ u64 ffma2(u64 a, u64 b, u64 c) {
    u64 d; asm("fma.rn.f32x2 %0, %1, %2, %3;" : "=l"(d) : "l"(a), "l"(b), "l"(c)); return d;
}
__device__ __forceinline__ void unpack2(u64 v, float& lo, float& hi) {
    asm("mov.b64 {%0, %1}, %2;" : "=f"(lo), "=f"(hi) : "l"(v));
}

// One t-step for this lane's 4 rows of its group's batch.
// KEY: one LDS.128 serves all 4 groups at once (different slots, distinct
// banks), so LDS instructions per batch-step = 2 — the crossbar (1/SM, the
// true bottleneck) is finally subcritical vs the fma pipes (4/SM).
// h streamed through a 2-deep ulonglong2 ring: live set 8 regs (no preload).
__device__ __forceinline__ void rnn_step(
    float x,
    const u64 (&w)[RPT][KP],
    const float (&wih)[RPT],
    const float (&bm)[RPT],
    const float* hsrc,    // group slot base (32 floats, pads zero)
    float* hdst)          // other buffer, this lane's float4
{
    const ulonglong2* hp = reinterpret_cast<const ulonglong2*>(hsrc);
    ulonglong2 rb0 = hp[0];
    ulonglong2 rb1 = hp[1];

    u64 a[RPT];
#pragma unroll
    for (int r = 0; r < RPT; r++) {
        a[r] = fmul2(w[r][0], rb0.x);
        a[r] = ffma2(w[r][1], rb0.y, a[r]);
    }
    rb0 = hp[2];
#pragma unroll
    for (int r = 0; r < RPT; r++) {
        a[r] = ffma2(w[r][2], rb1.x, a[r]);
        a[r] = ffma2(w[r][3], rb1.y, a[r]);
    }
    rb1 = hp[3];
#pragma unroll
    for (int r = 0; r < RPT; r++) {
        a[r] = ffma2(w[r][4], rb0.x, a[r]);
        a[r] = ffma2(w[r][5], rb0.y, a[r]);
    }
    rb0 = hp[4];
#pragma unroll
    for (int r = 0; r < RPT; r++) {
        a[r] = ffma2(w[r][6], rb1.x, a[r]);
        a[r] = ffma2(w[r][7], rb1.y, a[r]);
    }
    rb1 = hp[5];
#pragma unroll
    for (int r = 0; r < RPT; r++) {
        a[r] = ffma2(w[r][8], rb0.x, a[r]);
        a[r] = ffma2(w[r][9], rb0.y, a[r]);
    }
    rb0 = hp[6];
#pragma unroll
    for (int r = 0; r < RPT; r++) {
        a[r] = ffma2(w[r][10], rb1.x, a[r]);
        a[r] = ffma2(w[r][11], rb1.y, a[r]);
    }
    rb1 = hp[7];
#pragma unroll
    for (int r = 0; r < RPT; r++) {
        a[r] = ffma2(w[r][12], rb0.x, a[r]);
        a[r] = ffma2(w[r][13], rb0.y, a[r]);
    }
#pragma unroll
    for (int r = 0; r < RPT; r++) {     // pair 14 (pair 15 = zero pad: skip)
        a[r] = ffma2(w[r][14], rb1.x, a[r]);
    }

    float hv[RPT];
#pragma unroll
    for (int r = 0; r < RPT; r++) {
        float lo, hi;
        unpack2(a[r], lo, hi);
        float z = fmaf(x, wih[r], lo + hi);
        // modReLU: copysign(relu(|z|+b), z); z==0 -> +0 (pad rows stay 0)
        float m = fmaxf(fabsf(z) + bm[r], 0.0f);
        hv[r] = copysignf(m, z);
    }
    *reinterpret_cast<float4*>(hdst) = make_float4(hv[0], hv[1], hv[2], hv[3]);
    // Warp-synchronous exchange (validated R12): converged warp, STS->LDS
    // program order on hbuf; compiler-only fence at the step boundary.
    asm volatile("" ::: "memory");
}

extern "C" __global__ void __launch_bounds__(TPB)
rnn_modrelu_kernel(const float* __restrict__ inputs,  // [B, T]
                   const float* __restrict__ W_ih,    // [H]
                   const float* __restrict__ W_hh,    // [H, H]
                   const float* __restrict__ b_mod,   // [H]
                   const float* __restrict__ W_lin,   // [C, H]
                   const float* __restrict__ b_lin,   // [C]
                   float* __restrict__ out)           // [B, C]
{
    __shared__ __align__(16) float hbuf[2][SLOTS][HSTR];

    const int lane = threadIdx.x;       // 0..31
    const int sub  = lane & (GRP - 1);  // 0..7 row-slice
    const int g    = lane >> 3;         // 0..3 batch group
    const int b    = blockIdx.x * SLOTS + g;

    // ---- register weight slice: 4 rows x 15 pairs = 120 regs ----
    u64 w[RPT][KP];
    float wih[RPT], bm[RPT];
#pragma unroll
    for (int r = 0; r < RPT; r++) {
        const int row = sub * RPT + r;
        if (row < RH) {
            const u64* wr = reinterpret_cast<const u64*>(W_hh + row * RH);
#pragma unroll
            for (int p = 0; p < KP; p++) w[r][p] = wr[p];
            wih[r] = W_ih[row];
            bm[r]  = b_mod[row];
        } else {            // rows 30,31: all-zero -> stay exactly 0 forever
#pragma unroll
            for (int p = 0; p < KP; p++) w[r][p] = 0ULL;
            wih[r] = 0.0f;
            bm[r]  = 0.0f;
        }
    }

    // h0 = 0 (each lane zeroes its float4 -> all 32 floats per slot covered)
    *reinterpret_cast<float4*>(&hbuf[0][g][sub * 4]) = make_float4(0, 0, 0, 0);
    __syncwarp();

    const float* xr = inputs + (size_t)b * RT;

#pragma unroll 1
    for (int t0 = 0; t0 < RT; t0 += 2) {
        const float2 x2 = *reinterpret_cast<const float2*>(xr + t0);
        rnn_step(x2.x, w, wih, bm, &hbuf[0][g][0], &hbuf[1][g][sub * 4]);
        rnn_step(x2.y, w, wih, bm, &hbuf[1][g][0], &hbuf[0][g][sub * 4]);
    }
    // T=784 even -> final h in buffer 0
    __syncwarp();   // one-time, before cross-lane classifier reads

    // ---- fused classifier: out[b][c] = h . W_lin[c] + b_lin[c] ----
    const float* hf = &hbuf[0][g][0];
#pragma unroll 1
    for (int c = sub; c < RC; c += GRP) {
        float acc = b_lin[c];
        const float* wl = W_lin + c * RH;
#pragma unroll
        for (int k = 0; k < RH; k++) acc = fmaf(hf[k], wl[k], acc);
        out[(size_t)b * RC + c] = acc;
    }
}

extern "C" void kernel_launch(void* const* d_in, const int* in_sizes, int n_in,
                              void* d_out, int out_size) {
    const float* inputs = (const float*)d_in[0];
    const float* W_ih   = (const float*)d_in[1];
    const float* W_hh   = (const float*)d_in[2];
    const float* b_mod  = (const float*)d_in[3];
    const float* W_lin  = (const float*)d_in[4];
    const float* b_lin  = (const float*)d_in[5];
    float* out = (float*)d_out;

    dim3 grid(RB / SLOTS);   // 2048 one-warp blocks; ~14/SM -> single pass
    dim3 block(TPB);
    rnn_modrelu_kernel<<<grid, block>>>(inputs, W_ih, W_hh, b_mod,
                                        W_lin, b_lin, out);
}

// round 14
// speedup vs baseline: 1.2635x; 1.0016x over previous
#include <cuda_runtime.h>
#include <cstdint>

// Model_25855703122577: inputs [8192,784,1] f32, W_ih[30,1], W_hh[30,30],
// b_mod[30], W_lin[10,30], b_lin[10] -> out [8192,10] f32
#define RB    8192
#define RT    784
#define RH    30
#define RC    10
#define GRP   8        // lanes per batch element (4 parallel groups per warp)
#define RPT   4        // rows per lane (8*4 = 32; rows 30,31 zero pads)
#define KP    15       // k-pairs (exact)
#define TPB   32       // one warp per block
#define SLOTS 4        // batches per warp (one per 8-lane group)
#define HSTR  36       // floats per slot (144B: groups land on distinct banks)

typedef unsigned long long u64;

__device__ __forceinline__ u64 fmul2(u64 a, u64 b) {
    u64 d; asm("mul.rn.f32x2 %0, %1, %2;" : "=l"(d) : "l"(a), "l"(b)); return d;
}
__device__ __forceinline__ u64 ffma2(u64 a, u64 b, u64 c) {
    u64 d; asm("fma.rn.f32x2 %0, %1, %2, %3;" : "=l"(d) : "l"(a), "l"(b), "l"(c)); return d;
}
__device__ __forceinline__ void unpack2(u64 v, float& lo, float& hi) {
    asm("mov.b64 {%0, %1}, %2;" : "=f"(lo), "=f"(hi) : "l"(v));
}

// One t-step for this lane's 4 rows of its group's batch (R13 body, proven).
__device__ __forceinline__ void rnn_step(
    float x,
    const u64 (&w)[RPT][KP],
    const float (&wih)[RPT],
    const float (&bm)[RPT],
    const float* hsrc,    // group slot base (32 floats, pads zero)
    float* hdst)          // other buffer, this lane's float4
{
    const ulonglong2* hp = reinterpret_cast<const ulonglong2*>(hsrc);
    ulonglong2 rb0 = hp[0];
    ulonglong2 rb1 = hp[1];

    u64 a[RPT];
#pragma unroll
    for (int r = 0; r < RPT; r++) {
        a[r] = fmul2(w[r][0], rb0.x);
        a[r] = ffma2(w[r][1], rb0.y, a[r]);
    }
    rb0 = hp[2];
#pragma unroll
    for (int r = 0; r < RPT; r++) {
        a[r] = ffma2(w[r][2], rb1.x, a[r]);
        a[r] = ffma2(w[r][3], rb1.y, a[r]);
    }
    rb1 = hp[3];
#pragma unroll
    for (int r = 0; r < RPT; r++) {
        a[r] = ffma2(w[r][4], rb0.x, a[r]);
        a[r] = ffma2(w[r][5], rb0.y, a[r]);
    }
    rb0 = hp[4];
#pragma unroll
    for (int r = 0; r < RPT; r++) {
        a[r] = ffma2(w[r][6], rb1.x, a[r]);
        a[r] = ffma2(w[r][7], rb1.y, a[r]);
    }
    rb1 = hp[5];
#pragma unroll
    for (int r = 0; r < RPT; r++) {
        a[r] = ffma2(w[r][8], rb0.x, a[r]);
        a[r] = ffma2(w[r][9], rb0.y, a[r]);
    }
    rb0 = hp[6];
#pragma unroll
    for (int r = 0; r < RPT; r++) {
        a[r] = ffma2(w[r][10], rb1.x, a[r]);
        a[r] = ffma2(w[r][11], rb1.y, a[r]);
    }
    rb1 = hp[7];
#pragma unroll
    for (int r = 0; r < RPT; r++) {
        a[r] = ffma2(w[r][12], rb0.x, a[r]);
        a[r] = ffma2(w[r][13], rb0.y, a[r]);
    }
#pragma unroll
    for (int r = 0; r < RPT; r++) {     // pair 14 (pair 15 = zero pad: skip)
        a[r] = ffma2(w[r][14], rb1.x, a[r]);
    }

    float hv[RPT];
#pragma unroll
    for (int r = 0; r < RPT; r++) {
        float lo, hi;
        unpack2(a[r], lo, hi);
        float z = fmaf(x, wih[r], lo + hi);
        // modReLU: copysign(relu(|z|+b), z); z==0 -> +0 (pad rows stay 0)
        float m = fmaxf(fabsf(z) + bm[r], 0.0f);
        hv[r] = copysignf(m, z);
    }
    *reinterpret_cast<float4*>(hdst) = make_float4(hv[0], hv[1], hv[2], hv[3]);
    // Warp-synchronous exchange (validated R12/R13): converged warp,
    // STS->LDS program order on hbuf; compiler-only fence per step.
    asm volatile("" ::: "memory");
}

extern "C" __global__ void __launch_bounds__(TPB)
rnn_modrelu_kernel(const float* __restrict__ inputs,  // [B, T]
                   const float* __restrict__ W_ih,    // [H]
                   const float* __restrict__ W_hh,    // [H, H]
                   const float* __restrict__ b_mod,   // [H]
                   const float* __restrict__ W_lin,   // [C, H]
                   const float* __restrict__ b_lin,   // [C]
                   float* __restrict__ out)           // [B, C]
{
    __shared__ __align__(16) float hbuf[2][SLOTS][HSTR];

    const int lane = threadIdx.x;       // 0..31
    const int sub  = lane & (GRP - 1);  // 0..7 row-slice
    const int g    = lane >> 3;         // 0..3 batch group
    const int b    = blockIdx.x * SLOTS + g;

    // ---- register weight slice: 4 rows x 15 pairs = 120 regs ----
    u64 w[RPT][KP];
    float wih[RPT], bm[RPT];
#pragma unroll
    for (int r = 0; r < RPT; r++) {
        const int row = sub * RPT + r;
        if (row < RH) {
            const u64* wr = reinterpret_cast<const u64*>(W_hh + row * RH);
#pragma unroll
            for (int p = 0; p < KP; p++) w[r][p] = wr[p];
            wih[r] = W_ih[row];
            bm[r]  = b_mod[row];
        } else {            // rows 30,31: all-zero -> stay exactly 0 forever
#pragma unroll
            for (int p = 0; p < KP; p++) w[r][p] = 0ULL;
            wih[r] = 0.0f;
            bm[r]  = 0.0f;
        }
    }

    // h0 = 0 (each lane zeroes its float4 -> all 32 floats per slot covered)
    *reinterpret_cast<float4*>(&hbuf[0][g][sub * 4]) = make_float4(0, 0, 0, 0);
    __syncwarp();

    // ---- phase skew: desynchronize co-resident warps so their LDS dead
    // windows and FMA bursts interleave instead of convoying. One-time
    // dependent-FMA chain, 0..50 links (~0..200 cyc vs ~700-cyc step period).
    {
        const int skew = (blockIdx.x % 6) * 10;
        float d = 1.0f;
#pragma unroll 1
        for (int i = 0; i < skew; i++) d = fmaf(d, 0.9999999f, 1e-9f);
        // keep the chain alive: write d*0 (= +0.0 exactly, d is positive
        // finite) into a pad float that is never read.
        hbuf[0][g][33] = d * 0.0f;
    }

    const float* xr = inputs + (size_t)b * RT;

#pragma unroll 1
    for (int t0 = 0; t0 < RT; t0 += 2) {
        const float2 x2 = *reinterpret_cast<const float2*>(xr + t0);
        rnn_step(x2.x, w, wih, bm, &hbuf[0][g][0], &hbuf[1][g][sub * 4]);
        rnn_step(x2.y, w, wih, bm, &hbuf[1][g][0], &hbuf[0][g][sub * 4]);
    }
    // T=784 even -> final h in buffer 0
    __syncwarp();   // one-time, before cross-lane classifier reads

    // ---- fused classifier: out[b][c] = h . W_lin[c] + b_lin[c] ----
    const float* hf = &hbuf[0][g][0];
#pragma unroll 1
    for (int c = sub; c < RC; c += GRP) {
        float acc = b_lin[c];
        const float* wl = W_lin + c * RH;
#pragma unroll
        for (int k = 0; k < RH; k++) acc = fmaf(hf[k], wl[k], acc);
        out[(size_t)b * RC + c] = acc;
    }
}

extern "C" void kernel_launch(void* const* d_in, const int* in_sizes, int n_in,
                              void* d_out, int out_size) {
    const float* inputs = (const float*)d_in[0];
    const float* W_ih   = (const float*)d_in[1];
    const float* W_hh   = (const float*)d_in[2];
    const float* b_mod  = (const float*)d_in[3];
    const float* W_lin  = (const float*)d_in[4];
    const float* b_lin  = (const float*)d_in[5];
    float* out = (float*)d_out;

    dim3 grid(RB / SLOTS);   // 2048 one-warp blocks
    dim3 block(TPB);
    rnn_modrelu_kernel<<<grid, block>>>(inputs, W_ih, W_hh, b_mod,
                                        W_lin, b_lin, out);
}